// round 5
// baseline (speedup 1.0000x reference)
#include <cuda_runtime.h>
#include <math.h>

#define B_ 2
#define T_ 1024
#define C_ 768
#define V_ 32000
#define L_ 4
#define NB_ 4
#define K_ 15
#define P_ 16
#define BT_ (B_*T_)
#define NBC_ (NB_*C_)
#define HC_ (C_/2)
#define EPS_ 1.1920929e-07f
#define SCALE_ 1.8137993642342178f

// ---------------- static device scratch (no allocations) ----------------
__device__ float g_x[BT_*C_];
__device__ float g_normx[BT_*C_];
__device__ float g_qman[BT_*C_];
__device__ float g_xs[BT_*C_];
__device__ float g_ret[BT_*C_];
__device__ float g_a[BT_*C_];
__device__ float g_norma[BT_*C_];
__device__ float g_k[BT_*C_];
__device__ float g_y[BT_*C_];
__device__ float g_u[BT_*C_];
__device__ float g_h384[BT_*HC_];
__device__ float g_coords[BT_*2];
__device__ float g_h1536[BT_*2*C_];
__device__ float g_h3072[BT_*4*C_];
__device__ float g_qbig[BT_*NBC_];
__device__ float g_vbig[BT_*NBC_];
__device__ float g_qrope[BT_*NBC_];
__device__ float g_att[(size_t)B_*NB_*T_*T_];
__device__ float g_cos[T_*HC_];
__device__ float g_sin[T_*HC_];
__device__ float g_rmax[B_*NB_*T_];
__device__ float g_resid[BT_];
__device__ float g_palT[P_*P_*C_];

// ---------------- helpers ----------------
__device__ __forceinline__ float leluf(float x){
    return x / (1.f + expf(-SCALE_*x));
}
__device__ __forceinline__ float softplusf(float x){
    return fmaxf(x, 0.f) + log1pf(expf(-fabsf(x)));
}
__device__ __forceinline__ float blockSum256(float v, float* sb){
    #pragma unroll
    for(int o=16;o>0;o>>=1) v += __shfl_xor_sync(0xffffffffu, v, o);
    if((threadIdx.x & 31) == 0) sb[threadIdx.x >> 5] = v;
    __syncthreads();
    float r = 0.f;
    #pragma unroll
    for(int w=0;w<8;w++) r += sb[w];
    __syncthreads();
    return r;
}

// ---------------- small kernels ----------------
__global__ void cossin_k(){
    int t = blockIdx.x;
    for(int i=threadIdx.x;i<HC_;i+=blockDim.x){
        float inv = powf(10000.f, -(float)(2*i)/(float)C_);
        float fr  = (float)t * inv;
        g_cos[t*HC_+i] = cosf(fr);
        g_sin[t*HC_+i] = sinf(fr);
    }
}

__global__ void embed_k(const int* __restrict__ idx, const float* __restrict__ wte,
                        float* __restrict__ X){
    int bt = blockIdx.x;
    const float* src = wte + (size_t)idx[bt]*C_;
    float* dst = X + (size_t)bt*C_;
    for(int c=threadIdx.x;c<C_;c+=blockDim.x) dst[c] = src[c];
}

__global__ void rmsnorm_k(const float* __restrict__ X, float* __restrict__ Y){
    __shared__ float sb[8];
    int row = blockIdx.x;
    const float* xp = X + (size_t)row*C_;
    float ss = 0.f;
    for(int c=threadIdx.x;c<C_;c+=256){ float v = xp[c]; ss += v*v; }
    ss = blockSum256(ss, sb);
    float r = rsqrtf(ss/(float)C_ + EPS_);
    float* yp = Y + (size_t)row*C_;
    for(int c=threadIdx.x;c<C_;c+=256) yp[c] = xp[c]*r;
}

__global__ void conv_k(const float* __restrict__ Xn, const float* __restrict__ W,
                       float* __restrict__ Xs){
    int bt = blockIdx.x; int t = bt & (T_-1);
    const float* base = Xn + (size_t)bt*C_;
    float* out = Xs + (size_t)bt*C_;
    for(int c=threadIdx.x;c<C_;c+=256){
        float s = 0.f;
        #pragma unroll
        for(int j=0;j<K_;j++){
            int dt = j - (K_-1);
            if(t + dt >= 0) s += base[dt*C_ + c] * W[c*K_ + j];
        }
        out[c] = s;
    }
}

__global__ void palt_k(const float* __restrict__ pal, float* __restrict__ palT){
    int i = blockIdx.x*256 + threadIdx.x;
    if(i < C_*P_*P_){
        int c = i / (P_*P_), p = i % (P_*P_);
        palT[p*C_ + c] = pal[i];
    }
}

__global__ void coords_k(const float* __restrict__ H, const float* __restrict__ W2,
                         float* __restrict__ Cd){
    __shared__ float sb[8], sb2[8];
    int bt = blockIdx.x;
    const float* h = H + (size_t)bt*HC_;
    float s0=0.f, s1=0.f;
    for(int k=threadIdx.x;k<HC_;k+=256){ float v=h[k]; s0+=v*W2[k*2]; s1+=v*W2[k*2+1]; }
    s0 = blockSum256(s0, sb);
    s1 = blockSum256(s1, sb2);
    if(threadIdx.x==0){ Cd[bt*2]=tanhf(s0); Cd[bt*2+1]=tanhf(s1); }
}

__global__ void sample_k(const float* __restrict__ Cd, const float* __restrict__ palT,
                         float* __restrict__ ret){
    int bt = blockIdx.x;
    float cx = Cd[bt*2+0], cy = Cd[bt*2+1];
    float ix = fminf(fmaxf((cx + 1.f)*0.5f*(float)(P_-1), 0.f), (float)(P_-1));
    float iy = fminf(fmaxf((cy + 1.f)*0.5f*(float)(P_-1), 0.f), (float)(P_-1));
    float x0f = floorf(ix), y0f = floorf(iy);
    float wx = ix - x0f, wy = iy - y0f;
    int x0 = (int)x0f, y0 = (int)y0f;
    int x1 = min(x0+1, P_-1), y1 = min(y0+1, P_-1);
    int i00=y0*P_+x0, i01=y0*P_+x1, i10=y1*P_+x0, i11=y1*P_+x1;
    float w00=(1.f-wx)*(1.f-wy), w01=wx*(1.f-wy), w10=(1.f-wx)*wy, w11=wx*wy;
    float* out = ret + (size_t)bt*C_;
    for(int c=threadIdx.x;c<C_;c+=256){
        out[c] = palT[i00*C_+c]*w00 + palT[i01*C_+c]*w01
               + palT[i10*C_+c]*w10 + palT[i11*C_+c]*w11;
    }
}

__global__ void qnormrope_k(const float* __restrict__ Qbig, float* __restrict__ Qr){
    __shared__ float sb[8];
    int id = blockIdx.x; int n = id & 3; int bt = id >> 2;
    int b = bt >> 10; int t = bt & (T_-1);
    const float* src = Qbig + (size_t)bt*NBC_ + n*C_;
    float ss = 0.f;
    for(int c=threadIdx.x;c<C_;c+=256){ float v = src[c]; ss += v*v; }
    ss = blockSum256(ss, sb);
    float r = rsqrtf(ss/(float)C_ + EPS_);
    float* dst = Qr + ((size_t)(b*NB_+n)*T_ + t)*C_;
    const float* cp = g_cos + t*HC_;
    const float* sp = g_sin + t*HC_;
    for(int i=threadIdx.x;i<HC_;i+=256){
        float x1 = src[2*i]*r, x2 = src[2*i+1]*r;
        dst[2*i]   = x1*cp[i] - x2*sp[i];
        dst[2*i+1] = x1*sp[i] + x2*cp[i];
    }
}

__global__ void krope_k(const float* __restrict__ Kin, float* __restrict__ Kout){
    int bt = blockIdx.x; int t = bt & (T_-1);
    const float* src = Kin + (size_t)bt*C_;
    float* dst = Kout + (size_t)bt*C_;
    const float* cp = g_cos + t*HC_;
    const float* sp = g_sin + t*HC_;
    for(int i=threadIdx.x;i<HC_;i+=256){
        float x1 = src[2*i], x2 = src[2*i+1];
        dst[2*i]   = x1*cp[i] - x2*sp[i];
        dst[2*i+1] = x1*sp[i] + x2*cp[i];
    }
}

__global__ void route_k(float* __restrict__ Att, float* __restrict__ Rmax,
                        float* __restrict__ Resid){
    __shared__ float sb[8];
    __shared__ int swon[NB_];
    int bt = blockIdx.x, b = bt>>10, t = bt & (T_-1);
    const size_t TT = (size_t)T_*T_;
    float* base = Att + (size_t)b*NB_*TT + (size_t)t*T_;
    if(threadIdx.x < NB_) swon[threadIdx.x]=0;
    __syncthreads();
    float lsum=0.f; int w0=0,w1=0,w2=0,w3=0;
    for(int s=threadIdx.x; s<=t; s+=256){
        float a0=base[s], a1=base[TT+s], a2=base[2*TT+s], a3=base[3*TT+s];
        float m = fmaxf(fmaxf(a0,a1),fmaxf(a2,a3));
        lsum += softplusf(m);
        w0 |= (a0==m); w1 |= (a1==m); w2 |= (a2==m); w3 |= (a3==m);
    }
    float S = blockSum256(lsum, sb);
    if(w0) atomicOr(&swon[0],1);
    if(w1) atomicOr(&swon[1],1);
    if(w2) atomicOr(&swon[2],1);
    if(w3) atomicOr(&swon[3],1);
    float minv = fminf(1.f/(S+1e-6f), 1.f);
    for(int s=threadIdx.x; s<T_; s+=256){
        if(s<=t){
            float a0=base[s], a1=base[TT+s], a2=base[2*TT+s], a3=base[3*TT+s];
            float m = fmaxf(fmaxf(a0,a1),fmaxf(a2,a3));
            float w = softplusf(m)*minv;
            base[s]      = (a0==m)? w:0.f;
            base[TT+s]   = (a1==m)? w:0.f;
            base[2*TT+s] = (a2==m)? w:0.f;
            base[3*TT+s] = (a3==m)? w:0.f;
        } else {
            base[s]=0.f; base[TT+s]=0.f; base[2*TT+s]=0.f; base[3*TT+s]=0.f;
        }
    }
    __syncthreads();
    if(threadIdx.x==0){
        Resid[bt] = 1.f - S*minv;
        for(int n=0;n<NB_;n++)
            Rmax[(b*NB_+n)*T_+t] = (t < T_-1) ? 1.f : (swon[n] ? 1.f : 0.f);
    }
}

__global__ void sink_k(float* __restrict__ Y, const float* __restrict__ Rmax,
                       const float* __restrict__ Resid,
                       const float* __restrict__ sbn, const float* __restrict__ srn){
    int bt = blockIdx.x; int b = bt >> 10; int t = bt & (T_-1);
    float r = Resid[bt];
    float rm[NB_];
    #pragma unroll
    for(int n=0;n<NB_;n++) rm[n] = Rmax[(b*NB_+n)*T_ + t];
    float* yp = Y + (size_t)bt*C_;
    for(int c=threadIdx.x;c<C_;c+=256){
        float add = r * srn[c];
        #pragma unroll
        for(int n=0;n<NB_;n++) add += rm[n] * sbn[n*C_ + c];
        yp[c] += add;
    }
}

__global__ void cumsum_k(const float* __restrict__ Na, const float* __restrict__ U,
                         float* __restrict__ Xo){
    int b = blockIdx.x / 3;
    int c = (blockIdx.x % 3)*256 + threadIdx.x;
    size_t base = (size_t)b*T_*C_ + c;
    float run = 0.f;
    #pragma unroll 4
    for(int t=0;t<T_;t++){
        size_t o = base + (size_t)t*C_;
        run += Na[o];
        Xo[o] = U[o] + run/(float)(t+1);
    }
}

// ---------------- SGEMM 128x128x8, 256 threads, 8x8/thread ----------------
// EPI: 0 none, 1 lelu. RES: add residual.
template<int EPI, int RES>
__global__ void __launch_bounds__(256) sgemm_k(
    const float* __restrict__ A, const float* __restrict__ Bw,
    const float* __restrict__ Res, float* __restrict__ Out,
    int M, int N, int Kd)
{
    __shared__ float As[8][128];
    __shared__ float Bs[8][128];
    const int tid = threadIdx.x;
    const int tx = tid & 15, ty = tid >> 4;
    const int row0 = blockIdx.y*128, col0 = blockIdx.x*128;
    const int am = tid >> 1, ak = (tid & 1)*4;
    const int bk = tid >> 5, bn = (tid & 31)*4;
    float acc[8][8] = {};
    for(int k0=0;k0<Kd;k0+=8){
        float4 av = *(const float4*)(A  + (size_t)(row0+am)*Kd + k0 + ak);
        float4 bv = *(const float4*)(Bw + (size_t)(k0+bk)*N + col0 + bn);
        __syncthreads();
        As[ak+0][am]=av.x; As[ak+1][am]=av.y; As[ak+2][am]=av.z; As[ak+3][am]=av.w;
        *(float4*)&Bs[bk][bn] = bv;
        __syncthreads();
        #pragma unroll
        for(int kk=0;kk<8;kk++){
            float a[8], b[8];
            *(float4*)(a)   = *(const float4*)&As[kk][ty*8];
            *(float4*)(a+4) = *(const float4*)&As[kk][ty*8+4];
            *(float4*)(b)   = *(const float4*)&Bs[kk][tx*8];
            *(float4*)(b+4) = *(const float4*)&Bs[kk][tx*8+4];
            #pragma unroll
            for(int i=0;i<8;i++)
                #pragma unroll
                for(int j=0;j<8;j++) acc[i][j] += a[i]*b[j];
        }
    }
    #pragma unroll
    for(int i=0;i<8;i++){
        int r = row0 + ty*8 + i;
        #pragma unroll
        for(int j=0;j<8;j++){
            int c = col0 + tx*8 + j;
            float v = acc[i][j];
            if(EPI==1) v = leluf(v);
            size_t o = (size_t)r*N + c;
            if(RES) v += Res[o];
            Out[o] = v;
        }
    }
}

// ---------------- QK: NT GEMM, att[z][t][s] = q[z,t,:].k[b,s,:]/sqrt(C) ----------------
__global__ void __launch_bounds__(256) qk_k(const float* __restrict__ Q,
        const float* __restrict__ Kk, float* __restrict__ Att)
{
    int z = blockIdx.z;
    int row0 = blockIdx.y*128;   // t
    int col0 = blockIdx.x*128;   // s
    if(col0 > row0 + 127) return;
    const float* A  = Q  + (size_t)z*T_*C_;
    const float* Bb = Kk + (size_t)(z >> 2)*T_*C_;
    float* Outp = Att + (size_t)z*T_*T_;
    __shared__ float As[8][128];
    __shared__ float Bs[8][128];
    const int tid = threadIdx.x, tx = tid & 15, ty = tid >> 4;
    const int am = tid >> 1, ak = (tid & 1)*4;
    float acc[8][8] = {};
    for(int k0=0;k0<C_;k0+=8){
        float4 av = *(const float4*)(A  + (size_t)(row0+am)*C_ + k0 + ak);
        float4 bv = *(const float4*)(Bb + (size_t)(col0+am)*C_ + k0 + ak);
        __syncthreads();
        As[ak+0][am]=av.x; As[ak+1][am]=av.y; As[ak+2][am]=av.z; As[ak+3][am]=av.w;
        Bs[ak+0][am]=bv.x; Bs[ak+1][am]=bv.y; Bs[ak+2][am]=bv.z; Bs[ak+3][am]=bv.w;
        __syncthreads();
        #pragma unroll
        for(int kk=0;kk<8;kk++){
            float a[8], b[8];
            *(float4*)(a)   = *(const float4*)&As[kk][ty*8];
            *(float4*)(a+4) = *(const float4*)&As[kk][ty*8+4];
            *(float4*)(b)   = *(const float4*)&Bs[kk][tx*8];
            *(float4*)(b+4) = *(const float4*)&Bs[kk][tx*8+4];
            #pragma unroll
            for(int i=0;i<8;i++)
                #pragma unroll
                for(int j=0;j<8;j++) acc[i][j] += a[i]*b[j];
        }
    }
    const float sc = rsqrtf((float)C_);
    #pragma unroll
    for(int i=0;i<8;i++){
        int r = row0 + ty*8 + i;
        #pragma unroll
        for(int j=0;j<8;j++)
            Outp[(size_t)r*T_ + col0 + tx*8 + j] = acc[i][j]*sc;
    }
}

// ---------------- AV: y[b,t,c] = sum_n sum_s comb[b,n,t,s]*v[b,s,n,c] ----------------
__global__ void __launch_bounds__(256) av_k(const float* __restrict__ Comb,
        const float* __restrict__ Vb, float* __restrict__ Y)
{
    int b = blockIdx.z;
    int row0 = blockIdx.y*128;   // t
    int col0 = blockIdx.x*128;   // c
    __shared__ float As[8][128];
    __shared__ float Bs[8][128];
    const int tid = threadIdx.x, tx = tid & 15, ty = tid >> 4;
    const int am = tid >> 1, ak = (tid & 1)*4;
    const int bk = tid >> 5, bn = (tid & 31)*4;
    float acc[8][8] = {};
    const int smax = row0 + 128;
    for(int n=0;n<NB_;n++){
        const float* A = Comb + (size_t)(b*NB_+n)*T_*T_;
        for(int s0=0;s0<smax;s0+=8){
            float4 av = *(const float4*)(A  + (size_t)(row0+am)*T_ + s0 + ak);
            float4 bv = *(const float4*)(Vb + (size_t)(b*T_+s0+bk)*NBC_ + n*C_ + col0 + bn);
            __syncthreads();
            As[ak+0][am]=av.x; As[ak+1][am]=av.y; As[ak+2][am]=av.z; As[ak+3][am]=av.w;
            *(float4*)&Bs[bk][bn] = bv;
            __syncthreads();
            #pragma unroll
            for(int kk=0;kk<8;kk++){
                float a[8], bfr[8];
                *(float4*)(a)     = *(const float4*)&As[kk][ty*8];
                *(float4*)(a+4)   = *(const float4*)&As[kk][ty*8+4];
                *(float4*)(bfr)   = *(const float4*)&Bs[kk][tx*8];
                *(float4*)(bfr+4) = *(const float4*)&Bs[kk][tx*8+4];
                #pragma unroll
                for(int i=0;i<8;i++)
                    #pragma unroll
                    for(int j=0;j<8;j++) acc[i][j] += a[i]*bfr[j];
            }
        }
    }
    #pragma unroll
    for(int i=0;i<8;i++){
        int t = row0 + ty*8 + i;
        #pragma unroll
        for(int j=0;j<8;j++)
            Y[(size_t)(b*T_+t)*C_ + col0 + tx*8 + j] = acc[i][j];
    }
}

// ---------------- host ----------------
static float* symaddr(const void* s){
    void* p = nullptr;
    cudaGetSymbolAddress(&p, s);
    return (float*)p;
}

extern "C" void kernel_launch(void* const* d_in, const int* in_sizes, int n_in,
                              void* d_out, int out_size)
{
    const int*   idx     = (const int*)  d_in[0];
    const float* wte     = (const float*)d_in[1];
    const float* lm_head = (const float*)d_in[2];
    const float* q_w     = (const float*)d_in[3];
    const float* k_w     = (const float*)d_in[4];
    const float* v_w     = (const float*)d_in[5];
    const float* o_w     = (const float*)d_in[6];
    const float* sink_r  = (const float*)d_in[7];
    const float* sink_b  = (const float*)d_in[8];
    const float* palette = (const float*)d_in[9];
    const float* conv_w  = (const float*)d_in[10];
    const float* nav_w1  = (const float*)d_in[11];
    const float* nav_w2  = (const float*)d_in[12];
    const float* out_w1  = (const float*)d_in[13];
    const float* out_w2  = (const float*)d_in[14];
    const float* m1fc    = (const float*)d_in[15];
    const float* m1pj    = (const float*)d_in[16];
    const float* m2fc    = (const float*)d_in[17];
    const float* m2pj    = (const float*)d_in[18];
    float* out = (float*)d_out;

    float* x     = symaddr(g_x);
    float* normx = symaddr(g_normx);
    float* qman  = symaddr(g_qman);
    float* xs    = symaddr(g_xs);
    float* ret   = symaddr(g_ret);
    float* a     = symaddr(g_a);
    float* norma = symaddr(g_norma);
    float* kbuf  = symaddr(g_k);
    float* y     = symaddr(g_y);
    float* u     = symaddr(g_u);
    float* h384  = symaddr(g_h384);
    float* coords= symaddr(g_coords);
    float* h1536 = symaddr(g_h1536);
    float* h3072 = symaddr(g_h3072);
    float* qbig  = symaddr(g_qbig);
    float* vbig  = symaddr(g_vbig);
    float* qrope = symaddr(g_qrope);
    float* att   = symaddr(g_att);
    float* rmax  = symaddr(g_rmax);
    float* resid = symaddr(g_resid);
    float* palT  = symaddr(g_palT);

    const int M = BT_;
    cossin_k<<<T_,256>>>();
    embed_k<<<BT_,256>>>(idx, wte, x);

    for(int l=0;l<L_;l++){
        const float* qw  = q_w   + (size_t)l*C_*NBC_;
        const float* kw  = k_w   + (size_t)l*C_*C_;
        const float* vw  = v_w   + (size_t)l*C_*NBC_;
        const float* ow  = o_w   + (size_t)l*C_*C_;
        const float* sr  = sink_r+ (size_t)l*C_;
        const float* sb  = sink_b+ (size_t)l*NB_*C_;
        const float* pal = palette + (size_t)l*C_*P_*P_;
        const float* cw  = conv_w+ (size_t)l*C_*K_;
        const float* nw1 = nav_w1+ (size_t)l*C_*HC_;
        const float* nw2 = nav_w2+ (size_t)l*HC_*2;
        const float* ow1 = out_w1+ (size_t)l*C_*2*C_;
        const float* ow2 = out_w2+ (size_t)l*2*C_*C_;
        const float* fc1 = m1fc  + (size_t)l*C_*4*C_;
        const float* pj1 = m1pj  + (size_t)l*4*C_*C_;
        const float* fc2 = m2fc  + (size_t)l*C_*4*C_;
        const float* pj2 = m2pj  + (size_t)l*4*C_*C_;

        rmsnorm_k<<<BT_,256>>>(x, normx);
        // manifold
        palt_k<<<(C_*P_*P_+255)/256,256>>>(pal, palT);
        conv_k<<<BT_,256>>>(normx, cw, xs);
        sgemm_k<1,0><<<dim3(3,16),256>>>(xs, nw1, nullptr, h384, M, HC_, C_);
        coords_k<<<BT_,256>>>(h384, nw2, coords);
        sample_k<<<BT_,256>>>(coords, palT, ret);
        sgemm_k<1,0><<<dim3(12,16),256>>>(ret, ow1, nullptr, h1536, M, 2*C_, C_);
        sgemm_k<0,0><<<dim3(6,16),256>>>(h1536, ow2, nullptr, qman, M, C_, 2*C_);
        // a = q + mlp1(norm(q))
        rmsnorm_k<<<BT_,256>>>(qman, y);
        sgemm_k<1,0><<<dim3(24,16),256>>>(y, fc1, nullptr, h3072, M, 4*C_, C_);
        sgemm_k<0,1><<<dim3(6,16),256>>>(h3072, pj1, qman, a, M, C_, 4*C_);
        rmsnorm_k<<<BT_,256>>>(a, norma);
        // attention
        sgemm_k<0,0><<<dim3(24,16),256>>>(norma, qw, nullptr, qbig, M, NBC_, C_);
        sgemm_k<0,0><<<dim3(24,16),256>>>(norma, vw, nullptr, vbig, M, NBC_, C_);
        sgemm_k<0,0><<<dim3(6,16),256>>>(normx, kw, nullptr, y, M, C_, C_);
        krope_k<<<BT_,256>>>(y, kbuf);
        qnormrope_k<<<BT_*NB_,256>>>(qbig, qrope);
        qk_k<<<dim3(8,8,B_*NB_),256>>>(qrope, kbuf, att);
        route_k<<<BT_,256>>>(att, rmax, resid);
        av_k<<<dim3(6,8,B_),256>>>(att, vbig, y);
        sink_k<<<BT_,256>>>(y, rmax, resid, sb, sr);
        sgemm_k<0,1><<<dim3(6,16),256>>>(y, ow, x, u, M, C_, C_);
        // u2 = u + mlp2(norm(u))
        rmsnorm_k<<<BT_,256>>>(u, normx);
        sgemm_k<1,0><<<dim3(24,16),256>>>(normx, fc2, nullptr, h3072, M, 4*C_, C_);
        sgemm_k<0,1><<<dim3(6,16),256>>>(h3072, pj2, u, y, M, C_, 4*C_);
        // x = u2 + cumsum(norm(a))/steps
        cumsum_k<<<B_*3,256>>>(norma, y, x);
    }

    rmsnorm_k<<<BT_,256>>>(x, normx);
    sgemm_k<0,0><<<dim3(V_/128,16),256>>>(normx, lm_head, nullptr, out, M, V_, C_);
}

// round 7
// speedup vs baseline: 1.7984x; 1.7984x over previous
#include <cuda_runtime.h>
#include <math.h>
#include <stdint.h>

#define B_ 2
#define T_ 1024
#define C_ 768
#define V_ 32000
#define L_ 4
#define NB_ 4
#define K_ 15
#define P_ 16
#define BT_ (B_*T_)
#define NBC_ (NB_*C_)
#define HC_ (C_/2)
#define EPS_ 1.1920929e-07f
#define SCALE_ 1.8137993642342178f

// ---------------- static device scratch (no allocations) ----------------
__device__ float g_x[BT_*C_];
__device__ float g_normx[BT_*C_];
__device__ float g_qman[BT_*C_];
__device__ float g_xs[BT_*C_];
__device__ float g_ret[BT_*C_];
__device__ float g_a[BT_*C_];
__device__ float g_norma[BT_*C_];
__device__ float g_k[BT_*C_];
__device__ float g_kT[B_*C_*T_];
__device__ float g_y[BT_*C_];
__device__ float g_u[BT_*C_];
__device__ float g_h384[BT_*HC_];
__device__ float g_coords[BT_*2];
__device__ float g_h1536[BT_*2*C_];
__device__ float g_h3072[BT_*4*C_];
__device__ float g_qbig[BT_*NBC_];
__device__ float g_vbig[BT_*NBC_];
__device__ float g_qrope[BT_*NBC_];
__device__ float g_att[(size_t)B_*NB_*T_*T_];
__device__ float g_cos[T_*HC_];
__device__ float g_sin[T_*HC_];
__device__ float g_rmax[B_*NB_*T_];
__device__ float g_resid[BT_];
__device__ float g_palT[P_*P_*C_];
__device__ float g_segsum[B_*8*C_];

// ---------------- helpers ----------------
__device__ __forceinline__ float leluf(float x){
    return x / (1.f + expf(-SCALE_*x));
}
__device__ __forceinline__ float softplusf(float x){
    return fmaxf(x, 0.f) + log1pf(expf(-fabsf(x)));
}
__device__ __forceinline__ float blockSum256(float v, float* sb){
    #pragma unroll
    for(int o=16;o>0;o>>=1) v += __shfl_xor_sync(0xffffffffu, v, o);
    if((threadIdx.x & 31) == 0) sb[threadIdx.x >> 5] = v;
    __syncthreads();
    float r = 0.f;
    #pragma unroll
    for(int w=0;w<8;w++) r += sb[w];
    __syncthreads();
    return r;
}
__device__ __forceinline__ uint32_t f2tf32(float x){
    uint32_t r;
    asm("cvt.rna.tf32.f32 %0, %1;" : "=r"(r) : "f"(x));
    return r;
}
__device__ __forceinline__ void split_tf32(float x, uint32_t& hi, uint32_t& lo){
    hi = f2tf32(x);
    lo = f2tf32(x - __uint_as_float(hi));
}
__device__ __forceinline__ void mma_tf32(float* d, const uint32_t* a, const uint32_t* b){
    asm volatile(
      "mma.sync.aligned.m16n8k8.row.col.f32.tf32.tf32.f32 "
      "{%0,%1,%2,%3},{%4,%5,%6,%7},{%8,%9},{%0,%1,%2,%3};"
      : "+f"(d[0]),"+f"(d[1]),"+f"(d[2]),"+f"(d[3])
      : "r"(a[0]),"r"(a[1]),"r"(a[2]),"r"(a[3]), "r"(b[0]),"r"(b[1]));
}

// ---------------- small kernels ----------------
__global__ void cossin_k(){
    int t = blockIdx.x;
    for(int i=threadIdx.x;i<HC_;i+=blockDim.x){
        float inv = powf(10000.f, -(float)(2*i)/(float)C_);
        float fr  = (float)t * inv;
        g_cos[t*HC_+i] = cosf(fr);
        g_sin[t*HC_+i] = sinf(fr);
    }
}

__global__ void embed_k(const int* __restrict__ idx, const float* __restrict__ wte,
                        float* __restrict__ X){
    int bt = blockIdx.x;
    const float* src = wte + (size_t)idx[bt]*C_;
    float* dst = X + (size_t)bt*C_;
    for(int c=threadIdx.x;c<C_;c+=blockDim.x) dst[c] = src[c];
}

__global__ void rmsnorm_k(const float* __restrict__ X, float* __restrict__ Y){
    __shared__ float sb[8];
    int row = blockIdx.x;
    const float* xp = X + (size_t)row*C_;
    float ss = 0.f;
    for(int c=threadIdx.x;c<C_;c+=256){ float v = xp[c]; ss += v*v; }
    ss = blockSum256(ss, sb);
    float r = rsqrtf(ss/(float)C_ + EPS_);
    float* yp = Y + (size_t)row*C_;
    for(int c=threadIdx.x;c<C_;c+=256) yp[c] = xp[c]*r;
}

__global__ void conv_k(const float* __restrict__ Xn, const float* __restrict__ W,
                       float* __restrict__ Xs){
    int bt = blockIdx.x; int t = bt & (T_-1);
    const float* base = Xn + (size_t)bt*C_;
    float* out = Xs + (size_t)bt*C_;
    for(int c=threadIdx.x;c<C_;c+=256){
        float s = 0.f;
        #pragma unroll
        for(int j=0;j<K_;j++){
            int dt = j - (K_-1);
            if(t + dt >= 0) s += base[dt*C_ + c] * W[c*K_ + j];
        }
        out[c] = s;
    }
}

__global__ void palt_k(const float* __restrict__ pal, float* __restrict__ palT){
    int i = blockIdx.x*256 + threadIdx.x;
    if(i < C_*P_*P_){
        int c = i / (P_*P_), p = i % (P_*P_);
        palT[p*C_ + c] = pal[i];
    }
}

__global__ void coords_k(const float* __restrict__ H, const float* __restrict__ W2,
                         float* __restrict__ Cd){
    __shared__ float sb[8], sb2[8];
    int bt = blockIdx.x;
    const float* h = H + (size_t)bt*HC_;
    float s0=0.f, s1=0.f;
    for(int k=threadIdx.x;k<HC_;k+=256){ float v=h[k]; s0+=v*W2[k*2]; s1+=v*W2[k*2+1]; }
    s0 = blockSum256(s0, sb);
    s1 = blockSum256(s1, sb2);
    if(threadIdx.x==0){ Cd[bt*2]=tanhf(s0); Cd[bt*2+1]=tanhf(s1); }
}

__global__ void sample_k(const float* __restrict__ Cd, const float* __restrict__ palT,
                         float* __restrict__ ret){
    int bt = blockIdx.x;
    float cx = Cd[bt*2+0], cy = Cd[bt*2+1];
    float ix = fminf(fmaxf((cx + 1.f)*0.5f*(float)(P_-1), 0.f), (float)(P_-1));
    float iy = fminf(fmaxf((cy + 1.f)*0.5f*(float)(P_-1), 0.f), (float)(P_-1));
    float x0f = floorf(ix), y0f = floorf(iy);
    float wx = ix - x0f, wy = iy - y0f;
    int x0 = (int)x0f, y0 = (int)y0f;
    int x1 = min(x0+1, P_-1), y1 = min(y0+1, P_-1);
    int i00=y0*P_+x0, i01=y0*P_+x1, i10=y1*P_+x0, i11=y1*P_+x1;
    float w00=(1.f-wx)*(1.f-wy), w01=wx*(1.f-wy), w10=(1.f-wx)*wy, w11=wx*wy;
    float* out = ret + (size_t)bt*C_;
    for(int c=threadIdx.x;c<C_;c+=256){
        out[c] = palT[i00*C_+c]*w00 + palT[i01*C_+c]*w01
               + palT[i10*C_+c]*w10 + palT[i11*C_+c]*w11;
    }
}

// norm + rope + fold in 1/sqrt(C) attention scale
__global__ void qnormrope_k(const float* __restrict__ Qbig, float* __restrict__ Qr){
    __shared__ float sb[8];
    int id = blockIdx.x; int n = id & 3; int bt = id >> 2;
    int b = bt >> 10; int t = bt & (T_-1);
    const float* src = Qbig + (size_t)bt*NBC_ + n*C_;
    float ss = 0.f;
    for(int c=threadIdx.x;c<C_;c+=256){ float v = src[c]; ss += v*v; }
    ss = blockSum256(ss, sb);
    float r = rsqrtf(ss/(float)C_ + EPS_) * rsqrtf((float)C_);
    float* dst = Qr + ((size_t)(b*NB_+n)*T_ + t)*C_;
    const float* cp = g_cos + t*HC_;
    const float* sp = g_sin + t*HC_;
    for(int i=threadIdx.x;i<HC_;i+=256){
        float x1 = src[2*i]*r, x2 = src[2*i+1]*r;
        dst[2*i]   = x1*cp[i] - x2*sp[i];
        dst[2*i+1] = x1*sp[i] + x2*cp[i];
    }
}

__global__ void krope_k(const float* __restrict__ Kin, float* __restrict__ Kout){
    int bt = blockIdx.x; int t = bt & (T_-1);
    const float* src = Kin + (size_t)bt*C_;
    float* dst = Kout + (size_t)bt*C_;
    const float* cp = g_cos + t*HC_;
    const float* sp = g_sin + t*HC_;
    for(int i=threadIdx.x;i<HC_;i+=256){
        float x1 = src[2*i], x2 = src[2*i+1];
        dst[2*i]   = x1*cp[i] - x2*sp[i];
        dst[2*i+1] = x1*sp[i] + x2*cp[i];
    }
}

// transpose k: KT[b][c][s] = K[b][s][c]
__global__ void ktrans_k(const float* __restrict__ Kr, float* __restrict__ KT){
    __shared__ float tile[32][33];
    int b = blockIdx.z;
    int s0 = blockIdx.x*32, c0 = blockIdx.y*32;
    int tx = threadIdx.x, ty = threadIdx.y;
    #pragma unroll
    for(int i=0;i<4;i++)
        tile[ty+i*8][tx] = Kr[((size_t)b*T_ + s0+ty+i*8)*C_ + c0+tx];
    __syncthreads();
    #pragma unroll
    for(int i=0;i<4;i++)
        KT[((size_t)b*C_ + c0+ty+i*8)*T_ + s0+tx] = tile[tx][ty+i*8];
}

__global__ void route_k(float* __restrict__ Att, float* __restrict__ Rmax,
                        float* __restrict__ Resid){
    __shared__ float sb[8];
    __shared__ int swon[NB_];
    int bt = blockIdx.x, b = bt>>10, t = bt & (T_-1);
    const size_t TT = (size_t)T_*T_;
    float* base = Att + (size_t)b*NB_*TT + (size_t)t*T_;
    if(threadIdx.x < NB_) swon[threadIdx.x]=0;
    __syncthreads();
    float lsum=0.f; int w0=0,w1=0,w2=0,w3=0;
    for(int s=threadIdx.x; s<=t; s+=256){
        float a0=base[s], a1=base[TT+s], a2=base[2*TT+s], a3=base[3*TT+s];
        float m = fmaxf(fmaxf(a0,a1),fmaxf(a2,a3));
        lsum += softplusf(m);
        w0 |= (a0==m); w1 |= (a1==m); w2 |= (a2==m); w3 |= (a3==m);
    }
    float S = blockSum256(lsum, sb);
    if(w0) atomicOr(&swon[0],1);
    if(w1) atomicOr(&swon[1],1);
    if(w2) atomicOr(&swon[2],1);
    if(w3) atomicOr(&swon[3],1);
    float minv = fminf(1.f/(S+1e-6f), 1.f);
    for(int s=threadIdx.x; s<T_; s+=256){
        if(s<=t){
            float a0=base[s], a1=base[TT+s], a2=base[2*TT+s], a3=base[3*TT+s];
            float m = fmaxf(fmaxf(a0,a1),fmaxf(a2,a3));
            float w = softplusf(m)*minv;
            base[s]      = (a0==m)? w:0.f;
            base[TT+s]   = (a1==m)? w:0.f;
            base[2*TT+s] = (a2==m)? w:0.f;
            base[3*TT+s] = (a3==m)? w:0.f;
        } else {
            base[s]=0.f; base[TT+s]=0.f; base[2*TT+s]=0.f; base[3*TT+s]=0.f;
        }
    }
    __syncthreads();
    if(threadIdx.x==0){
        Resid[bt] = 1.f - S*minv;
        for(int n=0;n<NB_;n++)
            Rmax[(b*NB_+n)*T_+t] = (t < T_-1) ? 1.f : (swon[n] ? 1.f : 0.f);
    }
}

__global__ void sink_k(float* __restrict__ Y, const float* __restrict__ Rmax,
                       const float* __restrict__ Resid,
                       const float* __restrict__ sbn, const float* __restrict__ srn){
    int bt = blockIdx.x; int b = bt >> 10; int t = bt & (T_-1);
    float r = Resid[bt];
    float rm[NB_];
    #pragma unroll
    for(int n=0;n<NB_;n++) rm[n] = Rmax[(b*NB_+n)*T_ + t];
    float* yp = Y + (size_t)bt*C_;
    for(int c=threadIdx.x;c<C_;c+=256){
        float add = r * srn[c];
        #pragma unroll
        for(int n=0;n<NB_;n++) add += rm[n] * sbn[n*C_ + c];
        yp[c] += add;
    }
}

// cumsum phase 1: per-segment sums (segments of 128 t)
__global__ void seg1_k(const float* __restrict__ Na){
    int id = blockIdx.x;              // b*24 + seg*3 + ch
    int b = id/24, rest = id%24, seg = rest/3, ch = rest%3;
    int c = ch*256 + threadIdx.x;
    size_t base = ((size_t)b*T_ + (size_t)seg*128)*C_ + c;
    float s=0.f;
    #pragma unroll 8
    for(int t=0;t<128;t++) s += Na[base + (size_t)t*C_];
    g_segsum[(b*8+seg)*C_ + c] = s;
}
// cumsum phase 2: x = u + prefix/step
__global__ void seg2_k(const float* __restrict__ Na, const float* __restrict__ U,
                       float* __restrict__ Xo){
    int id = blockIdx.x;
    int b = id/24, rest = id%24, seg = rest/3, ch = rest%3;
    int c = ch*256 + threadIdx.x;
    float run = 0.f;
    for(int s=0;s<seg;s++) run += g_segsum[(b*8+s)*C_ + c];
    size_t base = ((size_t)b*T_ + (size_t)seg*128)*C_ + c;
    int t0 = seg*128;
    #pragma unroll 8
    for(int t=0;t<128;t++){
        size_t o = base + (size_t)t*C_;
        run += Na[o];
        Xo[o] = U[o] + run/(float)(t0+t+1);
    }
}

// ---------------- 3xTF32 tensor-core GEMM (fp32-grade accuracy) ----------------
// 128x128 CTA tile, k-step 16, 8 warps (warp tile 64x32), mma.m16n8k8 tf32.
// Each operand split hi/lo; acc += lo*hi + hi*lo + hi*hi.
// EPI: 0 none, 1 lelu.  RES: add Res.  ACC: add to existing Out.
// MODE: 0 plain, 1 K-truncate at row0+128 (AV), 2 skip tiles with col0>row0+127 (QK).
template<int EPI,int RES,int ACC,int MODE>
__global__ void __launch_bounds__(256) tgemm_k(
    const float* __restrict__ A, const float* __restrict__ Bw,
    const float* __restrict__ Res, float* __restrict__ Out,
    int N, int Kd, int lda, int ldb, int ldc,
    long long sAz, long long sBz, long long sCz)
{
    const int row0 = blockIdx.y*128, col0 = blockIdx.x*128;
    if(MODE==2 && col0 > row0 + 127) return;
    const int z = blockIdx.z;
    A   += (size_t)z*sAz;
    Bw  += (size_t)z*sBz;
    Out += (size_t)z*sCz;
    const float* ResZ = RES ? (Res + (size_t)z*sCz) : nullptr;

    __shared__ uint32_t AsH[128][20];
    __shared__ uint32_t AsL[128][20];
    __shared__ uint32_t BsH[16][136];
    __shared__ uint32_t BsL[16][136];

    const int tid = threadIdx.x;
    const int lane = tid & 31, wid = tid >> 5;
    const int wm = (wid & 1)*64, wn = (wid >> 1)*32;
    const int lg = lane >> 2, lt = lane & 3;

    const int ar = tid >> 2, ac = (tid & 3)*4;   // A: rows ar, ar+64; cols ac..ac+3
    const int br = wid,     bc = lane*4;         // B: rows br, br+8;  cols bc..bc+3

    int kend = Kd;
    if(MODE==1) kend = min(Kd, row0+128);

    float acc[4][4][4] = {};

    float4 pa0 = *(const float4*)(A + (size_t)(row0+ar)*lda + ac);
    float4 pa1 = *(const float4*)(A + (size_t)(row0+ar+64)*lda + ac);
    float4 pb0 = *(const float4*)(Bw + (size_t)br*ldb + col0 + bc);
    float4 pb1 = *(const float4*)(Bw + (size_t)(br+8)*ldb + col0 + bc);

    for(int k0=0; k0<kend; k0+=16){
        __syncthreads();
        {
            uint4 h, lo;
            split_tf32(pa0.x,h.x,lo.x); split_tf32(pa0.y,h.y,lo.y);
            split_tf32(pa0.z,h.z,lo.z); split_tf32(pa0.w,h.w,lo.w);
            *(uint4*)&AsH[ar][ac] = h;  *(uint4*)&AsL[ar][ac] = lo;
            split_tf32(pa1.x,h.x,lo.x); split_tf32(pa1.y,h.y,lo.y);
            split_tf32(pa1.z,h.z,lo.z); split_tf32(pa1.w,h.w,lo.w);
            *(uint4*)&AsH[ar+64][ac] = h;  *(uint4*)&AsL[ar+64][ac] = lo;
            split_tf32(pb0.x,h.x,lo.x); split_tf32(pb0.y,h.y,lo.y);
            split_tf32(pb0.z,h.z,lo.z); split_tf32(pb0.w,h.w,lo.w);
            *(uint4*)&BsH[br][bc] = h;  *(uint4*)&BsL[br][bc] = lo;
            split_tf32(pb1.x,h.x,lo.x); split_tf32(pb1.y,h.y,lo.y);
            split_tf32(pb1.z,h.z,lo.z); split_tf32(pb1.w,h.w,lo.w);
            *(uint4*)&BsH[br+8][bc] = h;  *(uint4*)&BsL[br+8][bc] = lo;
        }
        __syncthreads();
        if(k0+16 < kend){
            pa0 = *(const float4*)(A + (size_t)(row0+ar)*lda + k0+16 + ac);
            pa1 = *(const float4*)(A + (size_t)(row0+ar+64)*lda + k0+16 + ac);
            pb0 = *(const float4*)(Bw + (size_t)(k0+16+br)*ldb + col0 + bc);
            pb1 = *(const float4*)(Bw + (size_t)(k0+24+br)*ldb + col0 + bc);
        }
        #pragma unroll
        for(int sub=0; sub<2; sub++){
            const int kk = sub*8;
            uint32_t afh[4][4], afl[4][4], bfh[4][2], bfl[4][2];
            #pragma unroll
            for(int i=0;i<4;i++){
                int m = wm + i*16 + lg;
                afh[i][0] = AsH[m][kk+lt];
                afh[i][1] = AsH[m+8][kk+lt];
                afh[i][2] = AsH[m][kk+lt+4];
                afh[i][3] = AsH[m+8][kk+lt+4];
                afl[i][0] = AsL[m][kk+lt];
                afl[i][1] = AsL[m+8][kk+lt];
                afl[i][2] = AsL[m][kk+lt+4];
                afl[i][3] = AsL[m+8][kk+lt+4];
            }
            #pragma unroll
            for(int j=0;j<4;j++){
                int n = wn + j*8 + lg;
                bfh[j][0] = BsH[kk+lt][n];
                bfh[j][1] = BsH[kk+lt+4][n];
                bfl[j][0] = BsL[kk+lt][n];
                bfl[j][1] = BsL[kk+lt+4][n];
            }
            #pragma unroll
            for(int i=0;i<4;i++)
                #pragma unroll
                for(int j=0;j<4;j++){
                    mma_tf32(acc[i][j], afl[i], bfh[j]);
                    mma_tf32(acc[i][j], afh[i], bfl[j]);
                    mma_tf32(acc[i][j], afh[i], bfh[j]);
                }
        }
    }

    #pragma unroll
    for(int i=0;i<4;i++){
        int r0 = row0 + wm + i*16 + lg;
        #pragma unroll
        for(int j=0;j<4;j++){
            int c0 = col0 + wn + j*8 + lt*2;
            size_t o0 = (size_t)r0*ldc + c0;
            size_t o1 = o0 + (size_t)8*ldc;
            float v0=acc[i][j][0], v1=acc[i][j][1], v2=acc[i][j][2], v3=acc[i][j][3];
            if(EPI==1){ v0=leluf(v0); v1=leluf(v1); v2=leluf(v2); v3=leluf(v3); }
            if(RES){ v0+=ResZ[o0]; v1+=ResZ[o0+1]; v2+=ResZ[o1]; v3+=ResZ[o1+1]; }
            if(ACC){ v0+=Out[o0]; v1+=Out[o0+1]; v2+=Out[o1]; v3+=Out[o1+1]; }
            Out[o0]=v0; Out[o0+1]=v1; Out[o1]=v2; Out[o1+1]=v3;
        }
    }
}

// ---------------- host ----------------
static float* symaddr(const void* s){
    void* p = nullptr;
    cudaGetSymbolAddress(&p, s);
    return (float*)p;
}

extern "C" void kernel_launch(void* const* d_in, const int* in_sizes, int n_in,
                              void* d_out, int out_size)
{
    const int*   idx     = (const int*)  d_in[0];
    const float* wte     = (const float*)d_in[1];
    const float* lm_head = (const float*)d_in[2];
    const float* q_w     = (const float*)d_in[3];
    const float* k_w     = (const float*)d_in[4];
    const float* v_w     = (const float*)d_in[5];
    const float* o_w     = (const float*)d_in[6];
    const float* sink_r  = (const float*)d_in[7];
    const float* sink_b  = (const float*)d_in[8];
    const float* palette = (const float*)d_in[9];
    const float* conv_w  = (const float*)d_in[10];
    const float* nav_w1  = (const float*)d_in[11];
    const float* nav_w2  = (const float*)d_in[12];
    const float* out_w1  = (const float*)d_in[13];
    const float* out_w2  = (const float*)d_in[14];
    const float* m1fc    = (const float*)d_in[15];
    const float* m1pj    = (const float*)d_in[16];
    const float* m2fc    = (const float*)d_in[17];
    const float* m2pj    = (const float*)d_in[18];
    float* out = (float*)d_out;

    float* x     = symaddr(g_x);
    float* normx = symaddr(g_normx);
    float* qman  = symaddr(g_qman);
    float* xs    = symaddr(g_xs);
    float* ret   = symaddr(g_ret);
    float* a     = symaddr(g_a);
    float* norma = symaddr(g_norma);
    float* kbuf  = symaddr(g_k);
    float* kT    = symaddr(g_kT);
    float* y     = symaddr(g_y);
    float* u     = symaddr(g_u);
    float* h384  = symaddr(g_h384);
    float* coords= symaddr(g_coords);
    float* h1536 = symaddr(g_h1536);
    float* h3072 = symaddr(g_h3072);
    float* qbig  = symaddr(g_qbig);
    float* vbig  = symaddr(g_vbig);
    float* qrope = symaddr(g_qrope);
    float* att   = symaddr(g_att);
    float* rmax  = symaddr(g_rmax);
    float* resid = symaddr(g_resid);
    float* palT  = symaddr(g_palT);

    const long long TT = (long long)T_*T_;
    cossin_k<<<T_,256>>>();
    embed_k<<<BT_,256>>>(idx, wte, x);

    for(int l=0;l<L_;l++){
        const float* qw  = q_w   + (size_t)l*C_*NBC_;
        const float* kw  = k_w   + (size_t)l*C_*C_;
        const float* vw  = v_w   + (size_t)l*C_*NBC_;
        const float* ow  = o_w   + (size_t)l*C_*C_;
        const float* sr  = sink_r+ (size_t)l*C_;
        const float* sb  = sink_b+ (size_t)l*NB_*C_;
        const float* pal = palette + (size_t)l*C_*P_*P_;
        const float* cw  = conv_w+ (size_t)l*C_*K_;
        const float* nw1 = nav_w1+ (size_t)l*C_*HC_;
        const float* nw2 = nav_w2+ (size_t)l*HC_*2;
        const float* ow1 = out_w1+ (size_t)l*C_*2*C_;
        const float* ow2 = out_w2+ (size_t)l*2*C_*C_;
        const float* fc1 = m1fc  + (size_t)l*C_*4*C_;
        const float* pj1 = m1pj  + (size_t)l*4*C_*C_;
        const float* fc2 = m2fc  + (size_t)l*C_*4*C_;
        const float* pj2 = m2pj  + (size_t)l*4*C_*C_;

        rmsnorm_k<<<BT_,256>>>(x, normx);
        // ---- manifold ----
        palt_k<<<(C_*P_*P_+255)/256,256>>>(pal, palT);
        conv_k<<<BT_,256>>>(normx, cw, xs);
        tgemm_k<1,0,0,0><<<dim3(3,16),256>>>(xs, nw1, nullptr, h384, 384,768, 768,384,384, 0,0,0);
        coords_k<<<BT_,256>>>(h384, nw2, coords);
        sample_k<<<BT_,256>>>(coords, palT, ret);
        tgemm_k<1,0,0,0><<<dim3(12,16),256>>>(ret, ow1, nullptr, h1536, 1536,768, 768,1536,1536, 0,0,0);
        tgemm_k<0,0,0,0><<<dim3(6,16),256>>>(h1536, ow2, nullptr, qman, 768,1536, 1536,768,768, 0,0,0);
        // ---- a = q + mlp1(norm(q)) ----
        rmsnorm_k<<<BT_,256>>>(qman, y);
        tgemm_k<1,0,0,0><<<dim3(24,16),256>>>(y, fc1, nullptr, h3072, 3072,768, 768,3072,3072, 0,0,0);
        tgemm_k<0,1,0,0><<<dim3(6,16),256>>>(h3072, pj1, qman, a, 768,3072, 3072,768,768, 0,0,0);
        rmsnorm_k<<<BT_,256>>>(a, norma);
        // ---- attention ----
        tgemm_k<0,0,0,0><<<dim3(24,16),256>>>(norma, qw, nullptr, qbig, 3072,768, 768,3072,3072, 0,0,0);
        tgemm_k<0,0,0,0><<<dim3(24,16),256>>>(norma, vw, nullptr, vbig, 3072,768, 768,3072,3072, 0,0,0);
        tgemm_k<0,0,0,0><<<dim3(6,16),256>>>(normx, kw, nullptr, y, 768,768, 768,768,768, 0,0,0);
        krope_k<<<BT_,256>>>(y, kbuf);
        ktrans_k<<<dim3(T_/32,C_/32,B_),dim3(32,8)>>>(kbuf, kT);
        qnormrope_k<<<BT_*NB_,256>>>(qbig, qrope);
        for(int b=0;b<B_;b++){
            tgemm_k<0,0,0,2><<<dim3(8,8,NB_),256>>>(
                qrope + (size_t)b*NB_*T_*C_, kT + (size_t)b*C_*T_, nullptr,
                att + (size_t)b*NB_*TT,
                T_,C_, C_,T_,T_, (long long)T_*C_, 0, TT);
        }
        route_k<<<BT_,256>>>(att, rmax, resid);
        tgemm_k<0,0,0,1><<<dim3(6,8,B_),256>>>(att + 0*TT, vbig + 0*C_, nullptr, y,
                C_,T_, T_,NBC_,C_, (long long)NB_*TT, (long long)T_*NBC_, (long long)T_*C_);
        for(int n=1;n<NB_;n++){
            tgemm_k<0,0,1,1><<<dim3(6,8,B_),256>>>(att + (size_t)n*TT, vbig + n*C_, nullptr, y,
                C_,T_, T_,NBC_,C_, (long long)NB_*TT, (long long)T_*NBC_, (long long)T_*C_);
        }
        sink_k<<<BT_,256>>>(y, rmax, resid, sb, sr);
        tgemm_k<0,1,0,0><<<dim3(6,16),256>>>(y, ow, x, u, 768,768, 768,768,768, 0,0,0);
        // ---- u2 = u + mlp2(norm(u)) ----
        rmsnorm_k<<<BT_,256>>>(u, normx);
        tgemm_k<1,0,0,0><<<dim3(24,16),256>>>(normx, fc2, nullptr, h3072, 3072,768, 768,3072,3072, 0,0,0);
        tgemm_k<0,1,0,0><<<dim3(6,16),256>>>(h3072, pj2, u, y, 768,3072, 3072,768,768, 0,0,0);
        // ---- x = u2 + cumsum(norm(a))/steps ----
        seg1_k<<<B_*24,256>>>(norma);
        seg2_k<<<B_*24,256>>>(norma, y, x);
    }

    rmsnorm_k<<<BT_,256>>>(x, normx);
    tgemm_k<0,0,0,0><<<dim3(V_/128,16),256>>>(normx, lm_head, nullptr, out, V_,768, 768,V_,V_, 0,0,0);
}